// round 13
// baseline (speedup 1.0000x reference)
#include <cuda_runtime.h>
#include <stdint.h>

// Problem shape (fixed per reference)
#define BB 256
#define NN 1024
#define LL 128
#define MM 512
#define ROWS_PER_BLK 64    // 8 warps * 8 rows; always within one batch
#define PAIRS 4            // 4 row-pairs per warp -> 8 rows, MLP ~= 4 v8 loads

// 256-bit global accesses (sm_100+): one warp covers TWO 512-B rows per
// instruction (32 lanes * 32 B).
__device__ __forceinline__ void ldg_v8(float* d, const float* p) {
    unsigned r0, r1, r2, r3, r4, r5, r6, r7;
    asm("ld.global.nc.v8.b32 {%0,%1,%2,%3,%4,%5,%6,%7}, [%8];"
        : "=r"(r0), "=r"(r1), "=r"(r2), "=r"(r3),
          "=r"(r4), "=r"(r5), "=r"(r6), "=r"(r7) : "l"(p));
    d[0] = __uint_as_float(r0); d[1] = __uint_as_float(r1);
    d[2] = __uint_as_float(r2); d[3] = __uint_as_float(r3);
    d[4] = __uint_as_float(r4); d[5] = __uint_as_float(r5);
    d[6] = __uint_as_float(r6); d[7] = __uint_as_float(r7);
}
__device__ __forceinline__ void stg_v8_cs(float* p, const float* s) {
    asm volatile("st.global.cs.v8.b32 [%0], {%1,%2,%3,%4,%5,%6,%7,%8};"
        :: "l"(p),
           "r"(__float_as_uint(s[0])), "r"(__float_as_uint(s[1])),
           "r"(__float_as_uint(s[2])), "r"(__float_as_uint(s[3])),
           "r"(__float_as_uint(s[4])), "r"(__float_as_uint(s[5])),
           "r"(__float_as_uint(s[6])), "r"(__float_as_uint(s[7]))
        : "memory");
}

// Fused kernel, 8 rows per warp: each 256-thread block covers 64 consecutive
// rows of one batch; scans that batch's 512 indices into a 64-bit flag mask;
// each warp then handles 8 rows as 4 row-pairs (lanes 0-15 = even row,
// lanes 16-31 = odd row, 32 B/lane). All 4 pair-loads are front-batched
// before any consumer -> 4 outstanding 256-bit LDGs per warp.
// Unflagged row: v8 copy. Flagged row: endpoint reads + register linspace
// (endpoints parked in v[p][0..1] to avoid extra registers).
__global__ void __launch_bounds__(256)
fused_kernel(const float* __restrict__ in, float* __restrict__ out,
             const void* __restrict__ idx) {
    __shared__ unsigned int s_mask[2];

    int tid  = threadIdx.x;
    int lane = tid & 31;
    int warp = tid >> 5;
    int half = lane >> 4;      // 0: even row of pair, 1: odd row
    int sub  = lane & 15;      // 16 lanes per row, 8 floats per lane
    int row_lo = blockIdx.x * ROWS_PER_BLK;
    int b = row_lo >> 10;
    int local_lo = row_lo & (NN - 1);

    // ---- dtype probe (per warp, same cached 128 B) ----
    // True int64: first 16 values all in [0, NN). int32-read-as-int64:
    // value = lo + hi*2^32, out of range unless hi==0 (P ~ (1/1024)^16 ~ 0).
    long long pv = 0;
    if (lane < 16) pv = ((const long long*)idx)[lane];
    int ok = (pv >= 0 && pv < NN);
    unsigned ballot = __ballot_sync(0xffffffffu, ok);
    int is64 = ((ballot & 0xFFFFu) == 0xFFFFu);

    if (tid < 2) s_mask[tid] = 0u;
    __syncthreads();

    // ---- scan this batch's 512 indices; flag hits in [local_lo, +64) ----
    #pragma unroll
    for (int k = 0; k < MM / 256; k++) {        // 2 indices per thread
        int j = b * MM + tid + k * 256;
        int n = is64 ? (int)((const long long*)idx)[j]
                     : ((const int*)idx)[j];
        unsigned d = (unsigned)(n - local_lo);
        if (d < (unsigned)ROWS_PER_BLK)
            atomicOr(&s_mask[d >> 5], 1u << (d & 31));
    }
    __syncthreads();

    // Warp w owns rows [row_lo + w*8, +8): bits (w&3)*8 .. +7 of word w>>2.
    unsigned mword = s_mask[warp >> 2] >> ((warp & 3) * 8);
    int row0 = row_lo + warp * 8;

    float v[PAIRS][8];
    bool m[PAIRS];

    // ---- Phase 1: front-batched 256-bit loads (4 pairs, MLP ~= 4) ----
    #pragma unroll
    for (int p = 0; p < PAIRS; p++) {
        int r = 2 * p + half;                    // row-in-warp for this lane
        m[p] = (mword >> r) & 1u;
        const float* srow = in + (size_t)(row0 + r) * LL;
        if (!m[p]) {
            ldg_v8(v[p], srow + sub * 8);
        } else {
            float a = 0.f, e = 0.f;
            if (sub == 0)  a = srow[0];
            if (sub == 15) e = srow[LL - 1];
            v[p][0] = a; v[p][1] = e;            // park endpoints in payload
        }
    }

    // ---- Phase 2: linspace for flagged rows (per half-warp) ----
    const float inv = 1.0f / (float)(LL - 1);
    int base = sub * 8;
    #pragma unroll
    for (int p = 0; p < PAIRS; p++) {
        if (m[p]) {
            float start = __shfl_sync(0xffffffffu, v[p][0], half * 16);
            float end   = __shfl_sync(0xffffffffu, v[p][1], half * 16 + 15);
            float delta = end - start;
            #pragma unroll
            for (int i = 0; i < 8; i++)
                v[p][i] = start + delta * ((float)(base + i) * inv);
        }
    }

    // ---- Phase 3: 256-bit streaming stores ----
    #pragma unroll
    for (int p = 0; p < PAIRS; p++) {
        int r = 2 * p + half;
        stg_v8_cs(out + (size_t)(row0 + r) * LL + sub * 8, v[p]);
    }
}

extern "C" void kernel_launch(void* const* d_in, const int* in_sizes, int n_in,
                              void* d_out, int out_size) {
    const float* patches = (const float*)d_in[0];
    const void*  midx    = d_in[1];
    float*       out     = (float*)d_out;

    int blocks = (BB * NN) / ROWS_PER_BLK;   // 4096
    fused_kernel<<<blocks, 256>>>(patches, out, midx);
}

// round 14
// speedup vs baseline: 1.0092x; 1.0092x over previous
#include <cuda_runtime.h>
#include <stdint.h>

// Problem shape (fixed per reference)
#define BB 256
#define NN 1024
#define LL 128
#define MM 512
#define RPW 4              // rows per warp
#define ROWS_PER_BLK 32    // 8 warps * 4 rows; always within one batch

// Single fused kernel (champion R6 config): each 256-thread block covers 32
// consecutive rows of one batch. It scans that batch's 512 masked-indices
// (one vectorized load per thread) into a 32-bit block-local flag word, then
// writes its 32 rows: float4 copy for unflagged rows, register-generated
// linspace (endpoint reads only) for flagged rows. Loads/stores use
// streaming (.cs) hints; payload loads are front-batched for MLP ~= 4.
__global__ void __launch_bounds__(256)
fused_kernel(const float4* __restrict__ in, float4* __restrict__ out,
             const void* __restrict__ idx) {
    __shared__ unsigned int s_mask;

    int tid  = threadIdx.x;
    int lane = tid & 31;
    int warp = tid >> 5;
    int row_lo = blockIdx.x * ROWS_PER_BLK;    // block's first GLOBAL row
    int b = row_lo >> 10;                       // batch = row / NN
    int local_lo = row_lo & (NN - 1);           // block's first LOCAL row

    // ---- dtype probe (per warp, same cached 128 B) ----
    // True int64: first 16 values all in [0, NN). int32-read-as-int64:
    // value = lo + hi*2^32, out of range unless hi==0 (P ~ (1/1024)^16 ~ 0).
    long long pv = 0;
    if (lane < 16) pv = ((const long long*)idx)[lane];
    int ok = (pv >= 0 && pv < NN);
    unsigned ballot = __ballot_sync(0xffffffffu, ok);
    int is64 = ((ballot & 0xFFFFu) == 0xFFFFu);

    if (tid == 0) s_mask = 0u;
    __syncthreads();

    // ---- scan this batch's 512 indices (1 vector load per thread);
    //      flag hits in [local_lo, local_lo + 32) ----
    {
        int n0, n1;
        if (is64) {
            longlong2 v2 = ((const longlong2*)idx)[b * (MM / 2) + tid];
            n0 = (int)v2.x; n1 = (int)v2.y;
        } else {
            int2 v2 = ((const int2*)idx)[b * (MM / 2) + tid];
            n0 = v2.x; n1 = v2.y;
        }
        unsigned d0 = (unsigned)(n0 - local_lo);
        unsigned d1 = (unsigned)(n1 - local_lo);
        if (d0 < (unsigned)ROWS_PER_BLK) atomicOr(&s_mask, 1u << d0);
        if (d1 < (unsigned)ROWS_PER_BLK) atomicOr(&s_mask, 1u << d1);
    }
    __syncthreads();

    unsigned word = s_mask;
    int row0 = row_lo + warp * RPW;
    int sh = warp * RPW;

    bool m[RPW];
    #pragma unroll
    for (int r = 0; r < RPW; r++) m[r] = (word >> (sh + r)) & 1u;

    float4 v[RPW];
    float sv[RPW], ev[RPW];

    // ---- Phase 1: front-batched loads (MLP ~= 4) ----
    #pragma unroll
    for (int r = 0; r < RPW; r++) {
        const float* srow = (const float*)(in + (size_t)(row0 + r) * 32);
        if (!m[r]) {
            v[r] = __ldcs((const float4*)srow + lane);
        } else {
            float a = 0.f, e = 0.f;
            if (lane == 0)  a = __ldcs(&srow[0]);
            if (lane == 31) e = __ldcs(&srow[LL - 1]);
            sv[r] = a; ev[r] = e;
        }
    }

    // ---- Phase 2: linspace for flagged rows ----
    const float inv = 1.0f / (float)(LL - 1);
    int base = lane * 4;
    #pragma unroll
    for (int r = 0; r < RPW; r++) {
        if (m[r]) {
            float start = __shfl_sync(0xffffffffu, sv[r], 0);
            float end   = __shfl_sync(0xffffffffu, ev[r], 31);
            float delta = end - start;
            v[r].x = start + delta * ((float)(base + 0) * inv);
            v[r].y = start + delta * ((float)(base + 1) * inv);
            v[r].z = start + delta * ((float)(base + 2) * inv);
            v[r].w = start + delta * ((float)(base + 3) * inv);
        }
    }

    // ---- Phase 3: streaming stores ----
    #pragma unroll
    for (int r = 0; r < RPW; r++) {
        __stcs(out + (size_t)(row0 + r) * 32 + lane, v[r]);
    }
}

extern "C" void kernel_launch(void* const* d_in, const int* in_sizes, int n_in,
                              void* d_out, int out_size) {
    const float* patches = (const float*)d_in[0];
    const void*  midx    = d_in[1];
    float*       out     = (float*)d_out;

    int blocks = (BB * NN) / ROWS_PER_BLK;   // 8192
    fused_kernel<<<blocks, 256>>>((const float4*)patches, (float4*)out, midx);
}